// round 4
// baseline (speedup 1.0000x reference)
#include <cuda_runtime.h>
#include <math.h>

// Problem constants
#define Bz   8
#define SQv  1024
#define SKv  1024
#define Dm   512
#define Hh   8
#define HDv  64
#define DFFv 2048
#define Mrows 8192   // B*SQ == B*SK

// GEMM tiling
#define BM 128
#define BN 128
#define BK 16

// ---------------- scratch (static device memory; no runtime allocation) ----------------
__device__ float g_QH[4194304];     // [8192,512]
__device__ float g_KH[4194304];
__device__ float g_VH[4194304];
__device__ float g_ATT[4194304];
__device__ float g_F1[16777216];    // [8192,2048]
__device__ float g_S0[67108864];    // layer-0 pre-softmax scores [B,H,SQ,SK]
__device__ float g_SW[67108864];    // working scores / probabilities

// ---------------- block reductions (blockDim.x == 256 assumed) ----------------
__device__ __forceinline__ float blk_sum256(float v) {
    __shared__ float s[8];
    int tid = threadIdx.x;
    #pragma unroll
    for (int o = 16; o > 0; o >>= 1) v += __shfl_xor_sync(0xffffffffu, v, o);
    __syncthreads();                   // protect s reuse across calls
    if ((tid & 31) == 0) s[tid >> 5] = v;
    __syncthreads();
    float r = 0.f;
    #pragma unroll
    for (int i = 0; i < 8; i++) r += s[i];
    return r;
}

__device__ __forceinline__ float blk_max256(float v) {
    __shared__ float s[8];
    int tid = threadIdx.x;
    #pragma unroll
    for (int o = 16; o > 0; o >>= 1) v = fmaxf(v, __shfl_xor_sync(0xffffffffu, v, o));
    __syncthreads();
    if ((tid & 31) == 0) s[tid >> 5] = v;
    __syncthreads();
    float r = -3.4e38f;
    #pragma unroll
    for (int i = 0; i < 8; i++) r = fmaxf(r, s[i]);
    return r;
}

// ---------------- dense GEMM: C[M,N] = A[M,K] @ W[K,N] + bias (+ optional exact GELU) ----
// 128x128 block tile, BK=16, 256 threads, 8x8 per-thread microtile (split 4+4).
template<int ACT>
__global__ __launch_bounds__(256)
void gemm_kernel(const float* __restrict__ A, const float* __restrict__ W,
                 const float* __restrict__ bias, float* __restrict__ C,
                 int M, int N, int K)
{
    __shared__ float As[BK][BM + 4];   // transposed: As[k][m]
    __shared__ float Ws[BK][BN];       // Ws[k][n]

    const int tid = threadIdx.x;
    const int tx = tid & 15, ty = tid >> 4;
    const int bm = blockIdx.y * BM;
    const int bn = blockIdx.x * BN;

    float acc[8][8];
    #pragma unroll
    for (int i = 0; i < 8; i++)
        #pragma unroll
        for (int j = 0; j < 8; j++) acc[i][j] = 0.f;

    // A tile loader: 128x16 floats = 512 float4, 2 per thread
    const int aRow0 = tid >> 2;                 // 0..63
    const int aRow1 = aRow0 + 64;               // 64..127
    const int aC    = (tid & 3) * 4;            // 0,4,8,12
    // W tile loader: 16x128 floats = 512 float4, 2 per thread
    const int wRow0 = tid >> 5;                 // 0..7
    const int wRow1 = wRow0 + 8;                // 8..15
    const int wC    = (tid & 31) * 4;           // 0..124

    for (int kt = 0; kt < K; kt += BK) {
        float4 a0 = *(const float4*)&A[(size_t)(bm + aRow0) * K + kt + aC];
        float4 a1 = *(const float4*)&A[(size_t)(bm + aRow1) * K + kt + aC];
        float4 w0 = *(const float4*)&W[(size_t)(kt + wRow0) * N + bn + wC];
        float4 w1 = *(const float4*)&W[(size_t)(kt + wRow1) * N + bn + wC];
        __syncthreads();   // previous iteration's compute done before overwrite
        As[aC + 0][aRow0] = a0.x; As[aC + 1][aRow0] = a0.y; As[aC + 2][aRow0] = a0.z; As[aC + 3][aRow0] = a0.w;
        As[aC + 0][aRow1] = a1.x; As[aC + 1][aRow1] = a1.y; As[aC + 2][aRow1] = a1.z; As[aC + 3][aRow1] = a1.w;
        *(float4*)&Ws[wRow0][wC] = w0;
        *(float4*)&Ws[wRow1][wC] = w1;
        __syncthreads();
        #pragma unroll
        for (int k = 0; k < BK; k++) {
            float ar[8], br[8];
            *(float4*)&ar[0] = *(const float4*)&As[k][ty * 4];
            *(float4*)&ar[4] = *(const float4*)&As[k][64 + ty * 4];
            *(float4*)&br[0] = *(const float4*)&Ws[k][tx * 4];
            *(float4*)&br[4] = *(const float4*)&Ws[k][64 + tx * 4];
            #pragma unroll
            for (int i = 0; i < 8; i++)
                #pragma unroll
                for (int j = 0; j < 8; j++)
                    acc[i][j] = fmaf(ar[i], br[j], acc[i][j]);
        }
    }

    #pragma unroll
    for (int i = 0; i < 8; i++) {
        int row = bm + ((i < 4) ? (ty * 4 + i) : (64 + ty * 4 + (i - 4)));
        #pragma unroll
        for (int jj = 0; jj < 2; jj++) {
            int col = bn + (jj ? (64 + tx * 4) : (tx * 4));
            float4 r;
            r.x = acc[i][jj * 4 + 0] + bias[col + 0];
            r.y = acc[i][jj * 4 + 1] + bias[col + 1];
            r.z = acc[i][jj * 4 + 2] + bias[col + 2];
            r.w = acc[i][jj * 4 + 3] + bias[col + 3];
            if (ACT == 1) {  // exact GELU
                r.x = 0.5f * r.x * (1.f + erff(r.x * 0.7071067811865475f));
                r.y = 0.5f * r.y * (1.f + erff(r.y * 0.7071067811865475f));
                r.z = 0.5f * r.z * (1.f + erff(r.z * 0.7071067811865475f));
                r.w = 0.5f * r.w * (1.f + erff(r.w * 0.7071067811865475f));
            }
            *(float4*)&C[(size_t)row * N + col] = r;
        }
    }
}

// ---------------- attention scores: S[b,h,q,k] = eff * <QH_bq_h, KH_bk_h> (+ prev) -------
// grid (SK/64, SQ/64, B*H), 256 threads, 64x64 tile, full K=64 in one pass.
__global__ __launch_bounds__(256)
void scores_kernel(const float* __restrict__ QH, const float* __restrict__ KH,
                   const float* __restrict__ scale, const float* __restrict__ extra,
                   int layer, const float* __restrict__ prev, float* __restrict__ S)
{
    __shared__ float Qs[64][68];   // [d][q]
    __shared__ float Ks[64][68];   // [d][k]
    const int tid = threadIdx.x;
    const int tx = tid & 15, ty = tid >> 4;
    const int bh = blockIdx.z;
    const int b = bh >> 3, h = bh & 7;
    const int q0 = blockIdx.y * 64, k0 = blockIdx.x * 64;
    const float* Qb = QH + (size_t)b * SQv * Dm + h * HDv;
    const float* Kb = KH + (size_t)b * SKv * Dm + h * HDv;

    #pragma unroll
    for (int i = 0; i < 4; i++) {
        int f = tid + i * 256;
        int r = f >> 4, c = (f & 15) * 4;
        float4 qv = *(const float4*)&Qb[(size_t)(q0 + r) * Dm + c];
        float4 kv = *(const float4*)&Kb[(size_t)(k0 + r) * Dm + c];
        Qs[c + 0][r] = qv.x; Qs[c + 1][r] = qv.y; Qs[c + 2][r] = qv.z; Qs[c + 3][r] = qv.w;
        Ks[c + 0][r] = kv.x; Ks[c + 1][r] = kv.y; Ks[c + 2][r] = kv.z; Ks[c + 3][r] = kv.w;
    }
    __syncthreads();

    float acc[4][4];
    #pragma unroll
    for (int i = 0; i < 4; i++)
        #pragma unroll
        for (int j = 0; j < 4; j++) acc[i][j] = 0.f;

    #pragma unroll 8
    for (int d = 0; d < 64; d++) {
        float qr[4], kr[4];
        *(float4*)qr = *(const float4*)&Qs[d][ty * 4];
        *(float4*)kr = *(const float4*)&Ks[d][tx * 4];
        #pragma unroll
        for (int i = 0; i < 4; i++)
            #pragma unroll
            for (int j = 0; j < 4; j++)
                acc[i][j] = fmaf(qr[i], kr[j], acc[i][j]);
    }

    float e = extra[layer];
    e = fminf(fmaxf(e, 0.01f), 50.0f);
    const float eff = scale[layer] * e;

    #pragma unroll
    for (int i = 0; i < 4; i++) {
        size_t base = ((size_t)bh * SQv + (q0 + ty * 4 + i)) * SKv + k0 + tx * 4;
        float4 p = prev ? *(const float4*)&prev[base] : make_float4(0.f, 0.f, 0.f, 0.f);
        float4 o;
        o.x = fmaf(acc[i][0], eff, p.x);
        o.y = fmaf(acc[i][1], eff, p.y);
        o.z = fmaf(acc[i][2], eff, p.z);
        o.w = fmaf(acc[i][3], eff, p.w);
        *(float4*)&S[base] = o;
    }
}

// ---------------- row softmax over SK=1024, one block per row -------------------------
__global__ __launch_bounds__(256)
void softmax_kernel(const float* __restrict__ S, float* __restrict__ P)
{
    const size_t row = blockIdx.x;
    const int tid = threadIdx.x;
    float4 v = *(const float4*)&S[row * SKv + tid * 4];
    float m = fmaxf(fmaxf(v.x, v.y), fmaxf(v.z, v.w));
    m = blk_max256(m);
    float e0 = expf(v.x - m), e1 = expf(v.y - m), e2 = expf(v.z - m), e3 = expf(v.w - m);
    float s = blk_sum256(e0 + e1 + e2 + e3);
    float inv = 1.f / s;
    float4 o = make_float4(e0 * inv, e1 * inv, e2 * inv, e3 * inv);
    *(float4*)&P[row * SKv + tid * 4] = o;
}

// ---------------- O[b,q,h*64+d] = sum_k P[b,h,q,k] * VH[b,k,h*64+d] -------------------
// grid (SQ/64, B*H), 64q x 64d tile, K-loop over 1024.
__global__ __launch_bounds__(256)
void pv_kernel(const float* __restrict__ P, const float* __restrict__ VH, float* __restrict__ O)
{
    __shared__ float Ps[64][68];   // [k][q]
    __shared__ float Vs[64][68];   // [k][d]
    const int tid = threadIdx.x;
    const int tx = tid & 15, ty = tid >> 4;
    const int bh = blockIdx.y, b = bh >> 3, h = bh & 7;
    const int q0 = blockIdx.x * 64;
    const float* Pb = P + (size_t)bh * SQv * SKv;
    const float* Vb = VH + (size_t)b * SKv * Dm + h * HDv;

    float acc[4][4];
    #pragma unroll
    for (int i = 0; i < 4; i++)
        #pragma unroll
        for (int j = 0; j < 4; j++) acc[i][j] = 0.f;

    for (int kt = 0; kt < SKv; kt += 64) {
        __syncthreads();
        #pragma unroll
        for (int i = 0; i < 4; i++) {
            int f = tid + i * 256;
            int r = f >> 4, c = (f & 15) * 4;
            float4 pv = *(const float4*)&Pb[(size_t)(q0 + r) * SKv + kt + c];
            float4 vv = *(const float4*)&Vb[(size_t)(kt + r) * Dm + c];
            Ps[c + 0][r] = pv.x; Ps[c + 1][r] = pv.y; Ps[c + 2][r] = pv.z; Ps[c + 3][r] = pv.w;
            *(float4*)&Vs[r][c] = vv;
        }
        __syncthreads();
        #pragma unroll 8
        for (int k = 0; k < 64; k++) {
            float pr[4], vr[4];
            *(float4*)pr = *(const float4*)&Ps[k][ty * 4];
            *(float4*)vr = *(const float4*)&Vs[k][tx * 4];
            #pragma unroll
            for (int i = 0; i < 4; i++)
                #pragma unroll
                for (int j = 0; j < 4; j++)
                    acc[i][j] = fmaf(pr[i], vr[j], acc[i][j]);
        }
    }

    float* Ob = O + (size_t)b * SQv * Dm + h * HDv;
    #pragma unroll
    for (int i = 0; i < 4; i++) {
        float4 o = make_float4(acc[i][0], acc[i][1], acc[i][2], acc[i][3]);
        *(float4*)&Ob[(size_t)(q0 + ty * 4 + i) * Dm + tx * 4] = o;
    }
}

// ---------------- gated residual + post-LayerNorm (in-place on q) ----------------------
__global__ __launch_bounds__(256)
void addnorm_kernel(float* __restrict__ q, const float* __restrict__ delta,
                    const float* __restrict__ gate, const float* __restrict__ g,
                    const float* __restrict__ bb)
{
    const size_t row = blockIdx.x;
    const int tid = threadIdx.x;
    const float gt = gate[0];
    const float sp = (gt > 20.f) ? gt : log1pf(expf(gt));   // softplus

    float2 x = *(float2*)&q[row * Dm + tid * 2];
    float2 dd = *(const float2*)&delta[row * Dm + tid * 2];
    float y0 = x.x + sp * dd.x;
    float y1 = x.y + sp * dd.y;

    float s = blk_sum256(y0 + y1);
    float mu = s * (1.f / 512.f);
    float s2 = blk_sum256((y0 - mu) * (y0 - mu) + (y1 - mu) * (y1 - mu));
    float inv = rsqrtf(s2 * (1.f / 512.f) + 1e-5f);

    float2 o;
    o.x = (y0 - mu) * inv * g[tid * 2 + 0] + bb[tid * 2 + 0];
    o.y = (y1 - mu) * inv * g[tid * 2 + 1] + bb[tid * 2 + 1];
    *(float2*)&q[row * Dm + tid * 2] = o;
}

// ---------------- launcher -------------------------------------------------------------
extern "C" void kernel_launch(void* const* d_in, const int* in_sizes, int n_in,
                              void* d_out, int out_size)
{
    (void)in_sizes; (void)n_in; (void)out_size;
    const float* q_in  = (const float*)d_in[0];
    const float* k_in  = (const float*)d_in[1];
    const float* v_in  = (const float*)d_in[2];
    const float* WQ    = (const float*)d_in[3];
    const float* bQ    = (const float*)d_in[4];
    const float* WK    = (const float*)d_in[5];
    const float* bK    = (const float*)d_in[6];
    const float* WV    = (const float*)d_in[7];
    const float* bV    = (const float*)d_in[8];
    const float* WO    = (const float*)d_in[9];
    const float* bO    = (const float*)d_in[10];
    const float* Wf1   = (const float*)d_in[11];
    const float* bf1   = (const float*)d_in[12];
    const float* Wf2   = (const float*)d_in[13];
    const float* bf2   = (const float*)d_in[14];
    const float* ln1g  = (const float*)d_in[15];
    const float* ln1b  = (const float*)d_in[16];
    const float* ln2g  = (const float*)d_in[17];
    const float* ln2b  = (const float*)d_in[18];
    const float* scale = (const float*)d_in[19];
    const float* extra = (const float*)d_in[20];
    const float* gA    = (const float*)d_in[21];
    const float* gF    = (const float*)d_in[22];

    float *QH, *KH, *VH, *ATT, *F1, *S0, *SW;
    cudaGetSymbolAddress((void**)&QH, g_QH);
    cudaGetSymbolAddress((void**)&KH, g_KH);
    cudaGetSymbolAddress((void**)&VH, g_VH);
    cudaGetSymbolAddress((void**)&ATT, g_ATT);
    cudaGetSymbolAddress((void**)&F1, g_F1);
    cudaGetSymbolAddress((void**)&S0, g_S0);
    cudaGetSymbolAddress((void**)&SW, g_SW);

    float* qbuf = (float*)d_out;   // q lives in d_out the whole time
    cudaMemcpyAsync(qbuf, q_in, (size_t)Mrows * Dm * sizeof(float),
                    cudaMemcpyDeviceToDevice);

    const dim3 blk(256);
    const dim3 gP(Dm / BN, Mrows / BM);        // (4, 64)  N=512 GEMMs
    const dim3 gF1(DFFv / BN, Mrows / BM);     // (16, 64) FFN1

    for (int i = 0; i < 2; i++) {
        const size_t wofD = (size_t)i * Dm * Dm;
        const size_t wofF = (size_t)i * Dm * DFFv;

        gemm_kernel<0><<<gP, blk>>>(qbuf, WQ + wofD, bQ + i * Dm, QH, Mrows, Dm, Dm);
        gemm_kernel<0><<<gP, blk>>>(k_in, WK + wofD, bK + i * Dm, KH, Mrows, Dm, Dm);
        gemm_kernel<0><<<gP, blk>>>(v_in, WV + wofD, bV + i * Dm, VH, Mrows, Dm, Dm);

        const float* prev = (i == 0) ? nullptr : S0;
        float* Sout = (i == 0) ? S0 : SW;
        scores_kernel<<<dim3(SKv / 64, SQv / 64, Bz * Hh), blk>>>(QH, KH, scale, extra, i, prev, Sout);
        softmax_kernel<<<Bz * Hh * SQv, blk>>>(Sout, SW);
        pv_kernel<<<dim3(SQv / 64, Bz * Hh), blk>>>(SW, VH, QH);   // QH reused as attn-out

        gemm_kernel<0><<<gP, blk>>>(QH, WO + wofD, bO + i * Dm, ATT, Mrows, Dm, Dm);
        addnorm_kernel<<<Mrows, blk>>>(qbuf, ATT, gA + i, ln1g + (size_t)i * Dm, ln1b + (size_t)i * Dm);

        gemm_kernel<1><<<gF1, blk>>>(qbuf, Wf1 + wofF, bf1 + i * DFFv, F1, Mrows, DFFv, Dm);
        gemm_kernel<0><<<gP, blk>>>(F1, Wf2 + wofF, bf2 + i * Dm, ATT, Mrows, Dm, DFFv);
        addnorm_kernel<<<Mrows, blk>>>(qbuf, ATT, gF + i, ln2g + (size_t)i * Dm, ln2b + (size_t)i * Dm);
    }
}

// round 5
// speedup vs baseline: 1.9839x; 1.9839x over previous
#include <cuda_runtime.h>
#include <math.h>
#include <stdint.h>

// Problem constants
#define Bz   8
#define SQv  1024
#define SKv  1024
#define Dm   512
#define Hh   8
#define HDv  64
#define DFFv 2048
#define Mrows 8192   // B*SQ == B*SK

// Dense GEMM tiling
#define BM 128
#define BN 128
#define BK 16

// ---------------- scratch (static device memory; no runtime allocation) ----------------
__device__ float g_QH[4194304];     // [8192,512]
__device__ float g_KH[4194304];
__device__ float g_VH[4194304];
__device__ float g_ATT[4194304];
__device__ float g_F1[16777216];    // [8192,2048]
__device__ float g_S0[67108864];    // layer-0 pre-softmax scores [B,H,SQ,SK]
__device__ float g_SW[67108864];    // working scores / probabilities

// ---------------- tf32 helpers ---------------------------------------------------------
__device__ __forceinline__ unsigned f2tf(float x) {
    unsigned u;
    asm("cvt.rna.tf32.f32 %0, %1;" : "=r"(u) : "f"(x));
    return u;
}

__device__ __forceinline__ void mma_tf32(float c[4], const unsigned a[4], const unsigned b[2]) {
    asm volatile(
        "mma.sync.aligned.m16n8k8.row.col.f32.tf32.tf32.f32 "
        "{%0,%1,%2,%3}, {%4,%5,%6,%7}, {%8,%9}, {%0,%1,%2,%3};\n"
        : "+f"(c[0]), "+f"(c[1]), "+f"(c[2]), "+f"(c[3])
        : "r"(a[0]), "r"(a[1]), "r"(a[2]), "r"(a[3]), "r"(b[0]), "r"(b[1]));
}

// ---------------- block reductions (blockDim.x == 256 assumed) ----------------
__device__ __forceinline__ float blk_sum256(float v) {
    __shared__ float s[8];
    int tid = threadIdx.x;
    #pragma unroll
    for (int o = 16; o > 0; o >>= 1) v += __shfl_xor_sync(0xffffffffu, v, o);
    __syncthreads();
    if ((tid & 31) == 0) s[tid >> 5] = v;
    __syncthreads();
    float r = 0.f;
    #pragma unroll
    for (int i = 0; i < 8; i++) r += s[i];
    return r;
}

__device__ __forceinline__ float blk_max256(float v) {
    __shared__ float s[8];
    int tid = threadIdx.x;
    #pragma unroll
    for (int o = 16; o > 0; o >>= 1) v = fmaxf(v, __shfl_xor_sync(0xffffffffu, v, o));
    __syncthreads();
    if ((tid & 31) == 0) s[tid >> 5] = v;
    __syncthreads();
    float r = -3.4e38f;
    #pragma unroll
    for (int i = 0; i < 8; i++) r = fmaxf(r, s[i]);
    return r;
}

// ---------------- dense GEMM (tf32 tensor core): C = A[M,K] @ W[K,N] + bias (+GELU) ----
// 128x128 block tile, BK=16, 256 threads = 8 warps (2x4), warp tile 64x32,
// per-warp mma grid 4x4 of m16n8k8.
template<int ACT>
__global__ __launch_bounds__(256)
void gemm_tf32(const float* __restrict__ A, const float* __restrict__ W,
               const float* __restrict__ bias, float* __restrict__ C,
               int M, int N, int K)
{
    __shared__ unsigned As[BM][BK + 4];   // [m][k], stride 20 words -> LDS conflict-free
    __shared__ unsigned Ws[BK][BN + 8];   // [k][n], stride 136 words -> LDS conflict-free

    const int tid  = threadIdx.x;
    const int lane = tid & 31, warp = tid >> 5;
    const int wm = (warp >> 2) * 64;      // 0 or 64
    const int wn = (warp & 3) * 32;       // 0..96
    const int g = lane >> 2, tg = lane & 3;
    const int bm = blockIdx.y * BM, bn = blockIdx.x * BN;

    float acc[4][4][4];
    #pragma unroll
    for (int i = 0; i < 4; i++)
        #pragma unroll
        for (int j = 0; j < 4; j++)
            #pragma unroll
            for (int r = 0; r < 4; r++) acc[i][j][r] = 0.f;

    // A loader: 128x16 floats = 512 float4, 2 per thread
    const int aRow0 = tid >> 2, aRow1 = aRow0 + 64, aC = (tid & 3) * 4;
    // W loader: 16x128 floats = 512 float4, 2 per thread
    const int wRow0 = tid >> 5, wRow1 = wRow0 + 8, wC = lane * 4;

    for (int kt = 0; kt < K; kt += BK) {
        float4 a0 = *(const float4*)&A[(size_t)(bm + aRow0) * K + kt + aC];
        float4 a1 = *(const float4*)&A[(size_t)(bm + aRow1) * K + kt + aC];
        float4 w0 = *(const float4*)&W[(size_t)(kt + wRow0) * N + bn + wC];
        float4 w1 = *(const float4*)&W[(size_t)(kt + wRow1) * N + bn + wC];
        __syncthreads();   // previous iteration's compute done before overwrite
        *(uint4*)&As[aRow0][aC] = make_uint4(f2tf(a0.x), f2tf(a0.y), f2tf(a0.z), f2tf(a0.w));
        *(uint4*)&As[aRow1][aC] = make_uint4(f2tf(a1.x), f2tf(a1.y), f2tf(a1.z), f2tf(a1.w));
        *(uint4*)&Ws[wRow0][wC] = make_uint4(f2tf(w0.x), f2tf(w0.y), f2tf(w0.z), f2tf(w0.w));
        *(uint4*)&Ws[wRow1][wC] = make_uint4(f2tf(w1.x), f2tf(w1.y), f2tf(w1.z), f2tf(w1.w));
        __syncthreads();

        #pragma unroll
        for (int ks = 0; ks < BK; ks += 8) {
            unsigned af[4][4], bf[4][2];
            #pragma unroll
            for (int mi = 0; mi < 4; mi++) {
                int r = wm + mi * 16 + g;
                af[mi][0] = As[r][ks + tg];
                af[mi][1] = As[r + 8][ks + tg];
                af[mi][2] = As[r][ks + tg + 4];
                af[mi][3] = As[r + 8][ks + tg + 4];
            }
            #pragma unroll
            for (int nj = 0; nj < 4; nj++) {
                int c = wn + nj * 8 + g;
                bf[nj][0] = Ws[ks + tg][c];
                bf[nj][1] = Ws[ks + tg + 4][c];
            }
            #pragma unroll
            for (int mi = 0; mi < 4; mi++)
                #pragma unroll
                for (int nj = 0; nj < 4; nj++)
                    mma_tf32(acc[mi][nj], af[mi], bf[nj]);
        }
    }

    // epilogue: c0,c1 -> (row, col..col+1); c2,c3 -> (row+8, col..col+1)
    #pragma unroll
    for (int mi = 0; mi < 4; mi++) {
        #pragma unroll
        for (int nj = 0; nj < 4; nj++) {
            int row = bm + wm + mi * 16 + g;
            int col = bn + wn + nj * 8 + tg * 2;
            float b0 = bias[col], b1 = bias[col + 1];
            float2 v0 = make_float2(acc[mi][nj][0] + b0, acc[mi][nj][1] + b1);
            float2 v1 = make_float2(acc[mi][nj][2] + b0, acc[mi][nj][3] + b1);
            if (ACT == 1) {
                v0.x = 0.5f * v0.x * (1.f + erff(v0.x * 0.7071067811865475f));
                v0.y = 0.5f * v0.y * (1.f + erff(v0.y * 0.7071067811865475f));
                v1.x = 0.5f * v1.x * (1.f + erff(v1.x * 0.7071067811865475f));
                v1.y = 0.5f * v1.y * (1.f + erff(v1.y * 0.7071067811865475f));
            }
            *(float2*)&C[(size_t)row * N + col]       = v0;
            *(float2*)&C[(size_t)(row + 8) * N + col] = v1;
        }
    }
}

// ---------------- attention scores (tf32 mma): S = eff*(Q K^T) (+prev) -----------------
// 64x64 block tile over (q,k), full d=64 in one pass. 128 threads = 4 warps (2x2),
// warp tile 32x32, per-warp mma grid 2x4.
__global__ __launch_bounds__(128)
void scores_tf32(const float* __restrict__ QH, const float* __restrict__ KH,
                 const float* __restrict__ scale, const float* __restrict__ extra,
                 int layer, const float* __restrict__ prev, float* __restrict__ S)
{
    __shared__ unsigned Qs[64][72];   // [q][d]
    __shared__ unsigned Ks[64][72];   // [k][d]
    const int tid = threadIdx.x;
    const int lane = tid & 31, warp = tid >> 5;
    const int wm = (warp >> 1) * 32, wn = (warp & 1) * 32;
    const int g = lane >> 2, tg = lane & 3;
    const int bh = blockIdx.z, b = bh >> 3, h = bh & 7;
    const int q0 = blockIdx.y * 64, k0 = blockIdx.x * 64;
    const float* Qb = QH + (size_t)b * SQv * Dm + h * HDv;
    const float* Kb = KH + (size_t)b * SKv * Dm + h * HDv;

    #pragma unroll
    for (int i = 0; i < 8; i++) {
        int f = tid + i * 128;
        int r = f >> 4, c = (f & 15) * 4;
        float4 qv = *(const float4*)&Qb[(size_t)(q0 + r) * Dm + c];
        float4 kv = *(const float4*)&Kb[(size_t)(k0 + r) * Dm + c];
        *(uint4*)&Qs[r][c] = make_uint4(f2tf(qv.x), f2tf(qv.y), f2tf(qv.z), f2tf(qv.w));
        *(uint4*)&Ks[r][c] = make_uint4(f2tf(kv.x), f2tf(kv.y), f2tf(kv.z), f2tf(kv.w));
    }
    __syncthreads();

    float acc[2][4][4];
    #pragma unroll
    for (int i = 0; i < 2; i++)
        #pragma unroll
        for (int j = 0; j < 4; j++)
            #pragma unroll
            for (int r = 0; r < 4; r++) acc[i][j][r] = 0.f;

    #pragma unroll
    for (int ks = 0; ks < 64; ks += 8) {
        unsigned af[2][4], bf[4][2];
        #pragma unroll
        for (int mi = 0; mi < 2; mi++) {
            int r = wm + mi * 16 + g;
            af[mi][0] = Qs[r][ks + tg];
            af[mi][1] = Qs[r + 8][ks + tg];
            af[mi][2] = Qs[r][ks + tg + 4];
            af[mi][3] = Qs[r + 8][ks + tg + 4];
        }
        #pragma unroll
        for (int nj = 0; nj < 4; nj++) {
            int c = wn + nj * 8 + g;
            bf[nj][0] = Ks[c][ks + tg];
            bf[nj][1] = Ks[c][ks + tg + 4];
        }
        #pragma unroll
        for (int mi = 0; mi < 2; mi++)
            #pragma unroll
            for (int nj = 0; nj < 4; nj++)
                mma_tf32(acc[mi][nj], af[mi], bf[nj]);
    }

    float e = extra[layer];
    e = fminf(fmaxf(e, 0.01f), 50.0f);
    const float eff = scale[layer] * e;

    #pragma unroll
    for (int mi = 0; mi < 2; mi++) {
        #pragma unroll
        for (int nj = 0; nj < 4; nj++) {
            int row = q0 + wm + mi * 16 + g;
            int col = k0 + wn + nj * 8 + tg * 2;
            size_t b0 = ((size_t)bh * SQv + row) * SKv + col;
            size_t b1 = b0 + (size_t)8 * SKv;
            float2 p0 = prev ? *(const float2*)&prev[b0] : make_float2(0.f, 0.f);
            float2 p1 = prev ? *(const float2*)&prev[b1] : make_float2(0.f, 0.f);
            float2 o0 = make_float2(fmaf(acc[mi][nj][0], eff, p0.x),
                                    fmaf(acc[mi][nj][1], eff, p0.y));
            float2 o1 = make_float2(fmaf(acc[mi][nj][2], eff, p1.x),
                                    fmaf(acc[mi][nj][3], eff, p1.y));
            *(float2*)&S[b0] = o0;
            *(float2*)&S[b1] = o1;
        }
    }
}

// ---------------- P@V (tf32 mma): O[b,q,h*64+d] = sum_k P[b,h,q,k] * VH[b,k,h*64+d] ----
// 64(q) x 64(d) block, K-loop over SK in chunks of 64. 128 threads = 4 warps (2x2),
// warp tile 32x32.
__global__ __launch_bounds__(128)
void pv_tf32(const float* __restrict__ P, const float* __restrict__ VH,
             float* __restrict__ O)
{
    __shared__ unsigned Ps[64][72];   // [q][k]
    __shared__ unsigned Vs[64][72];   // [k][d]
    const int tid = threadIdx.x;
    const int lane = tid & 31, warp = tid >> 5;
    const int wm = (warp >> 1) * 32, wn = (warp & 1) * 32;
    const int g = lane >> 2, tg = lane & 3;
    const int bh = blockIdx.y, b = bh >> 3, h = bh & 7;
    const int q0 = blockIdx.x * 64;
    const float* Pb = P + (size_t)bh * SQv * SKv;
    const float* Vb = VH + (size_t)b * SKv * Dm + h * HDv;

    float acc[2][4][4];
    #pragma unroll
    for (int i = 0; i < 2; i++)
        #pragma unroll
        for (int j = 0; j < 4; j++)
            #pragma unroll
            for (int r = 0; r < 4; r++) acc[i][j][r] = 0.f;

    for (int kt = 0; kt < SKv; kt += 64) {
        __syncthreads();
        #pragma unroll
        for (int i = 0; i < 8; i++) {
            int f = tid + i * 128;
            int r = f >> 4, c = (f & 15) * 4;
            float4 pv = *(const float4*)&Pb[(size_t)(q0 + r) * SKv + kt + c];
            float4 vv = *(const float4*)&Vb[(size_t)(kt + r) * Dm + c];
            *(uint4*)&Ps[r][c] = make_uint4(f2tf(pv.x), f2tf(pv.y), f2tf(pv.z), f2tf(pv.w));
            *(uint4*)&Vs[r][c] = make_uint4(f2tf(vv.x), f2tf(vv.y), f2tf(vv.z), f2tf(vv.w));
        }
        __syncthreads();

        #pragma unroll
        for (int ks = 0; ks < 64; ks += 8) {
            unsigned af[2][4], bf[4][2];
            #pragma unroll
            for (int mi = 0; mi < 2; mi++) {
                int r = wm + mi * 16 + g;
                af[mi][0] = Ps[r][ks + tg];
                af[mi][1] = Ps[r + 8][ks + tg];
                af[mi][2] = Ps[r][ks + tg + 4];
                af[mi][3] = Ps[r + 8][ks + tg + 4];
            }
            #pragma unroll
            for (int nj = 0; nj < 4; nj++) {
                int c = wn + nj * 8 + g;
                bf[nj][0] = Vs[ks + tg][c];
                bf[nj][1] = Vs[ks + tg + 4][c];
            }
            #pragma unroll
            for (int mi = 0; mi < 2; mi++)
                #pragma unroll
                for (int nj = 0; nj < 4; nj++)
                    mma_tf32(acc[mi][nj], af[mi], bf[nj]);
        }
    }

    float* Ob = O + (size_t)b * SQv * Dm + h * HDv;
    #pragma unroll
    for (int mi = 0; mi < 2; mi++) {
        #pragma unroll
        for (int nj = 0; nj < 4; nj++) {
            int row = q0 + wm + mi * 16 + g;
            int col = wn + nj * 8 + tg * 2;
            *(float2*)&Ob[(size_t)row * Dm + col] =
                make_float2(acc[mi][nj][0], acc[mi][nj][1]);
            *(float2*)&Ob[(size_t)(row + 8) * Dm + col] =
                make_float2(acc[mi][nj][2], acc[mi][nj][3]);
        }
    }
}

// ---------------- row softmax over SK=1024, one block per row -------------------------
__global__ __launch_bounds__(256)
void softmax_kernel(const float* __restrict__ S, float* __restrict__ P)
{
    const size_t row = blockIdx.x;
    const int tid = threadIdx.x;
    float4 v = *(const float4*)&S[row * SKv + tid * 4];
    float m = fmaxf(fmaxf(v.x, v.y), fmaxf(v.z, v.w));
    m = blk_max256(m);
    float e0 = expf(v.x - m), e1 = expf(v.y - m), e2 = expf(v.z - m), e3 = expf(v.w - m);
    float s = blk_sum256(e0 + e1 + e2 + e3);
    float inv = 1.f / s;
    float4 o = make_float4(e0 * inv, e1 * inv, e2 * inv, e3 * inv);
    *(float4*)&P[row * SKv + tid * 4] = o;
}

// ---------------- gated residual + post-LayerNorm (in-place on q) ----------------------
__global__ __launch_bounds__(256)
void addnorm_kernel(float* __restrict__ q, const float* __restrict__ delta,
                    const float* __restrict__ gate, const float* __restrict__ g,
                    const float* __restrict__ bb)
{
    const size_t row = blockIdx.x;
    const int tid = threadIdx.x;
    const float gt = gate[0];
    const float sp = (gt > 20.f) ? gt : log1pf(expf(gt));   // softplus

    float2 x = *(float2*)&q[row * Dm + tid * 2];
    float2 dd = *(const float2*)&delta[row * Dm + tid * 2];
    float y0 = x.x + sp * dd.x;
    float y1 = x.y + sp * dd.y;

    float s = blk_sum256(y0 + y1);
    float mu = s * (1.f / 512.f);
    float s2 = blk_sum256((y0 - mu) * (y0 - mu) + (y1 - mu) * (y1 - mu));
    float inv = rsqrtf(s2 * (1.f / 512.f) + 1e-5f);

    float2 o;
    o.x = (y0 - mu) * inv * g[tid * 2 + 0] + bb[tid * 2 + 0];
    o.y = (y1 - mu) * inv * g[tid * 2 + 1] + bb[tid * 2 + 1];
    *(float2*)&q[row * Dm + tid * 2] = o;
}

// ---------------- launcher -------------------------------------------------------------
extern "C" void kernel_launch(void* const* d_in, const int* in_sizes, int n_in,
                              void* d_out, int out_size)
{
    (void)in_sizes; (void)n_in; (void)out_size;
    const float* q_in  = (const float*)d_in[0];
    const float* k_in  = (const float*)d_in[1];
    const float* v_in  = (const float*)d_in[2];
    const float* WQ    = (const float*)d_in[3];
    const float* bQ    = (const float*)d_in[4];
    const float* WK    = (const float*)d_in[5];
    const float* bK    = (const float*)d_in[6];
    const float* WV    = (const float*)d_in[7];
    const float* bV    = (const float*)d_in[8];
    const float* WO    = (const float*)d_in[9];
    const float* bO    = (const float*)d_in[10];
    const float* Wf1   = (const float*)d_in[11];
    const float* bf1   = (const float*)d_in[12];
    const float* Wf2   = (const float*)d_in[13];
    const float* bf2   = (const float*)d_in[14];
    const float* ln1g  = (const float*)d_in[15];
    const float* ln1b  = (const float*)d_in[16];
    const float* ln2g  = (const float*)d_in[17];
    const float* ln2b  = (const float*)d_in[18];
    const float* scale = (const float*)d_in[19];
    const float* extra = (const float*)d_in[20];
    const float* gA    = (const float*)d_in[21];
    const float* gF    = (const float*)d_in[22];

    float *QH, *KH, *VH, *ATT, *F1, *S0, *SW;
    cudaGetSymbolAddress((void**)&QH, g_QH);
    cudaGetSymbolAddress((void**)&KH, g_KH);
    cudaGetSymbolAddress((void**)&VH, g_VH);
    cudaGetSymbolAddress((void**)&ATT, g_ATT);
    cudaGetSymbolAddress((void**)&F1, g_F1);
    cudaGetSymbolAddress((void**)&S0, g_S0);
    cudaGetSymbolAddress((void**)&SW, g_SW);

    float* qbuf = (float*)d_out;   // q lives in d_out the whole time
    cudaMemcpyAsync(qbuf, q_in, (size_t)Mrows * Dm * sizeof(float),
                    cudaMemcpyDeviceToDevice);

    const dim3 gP(Dm / BN, Mrows / BM);        // (4, 64)  N=512 GEMMs
    const dim3 gF1(DFFv / BN, Mrows / BM);     // (16, 64) FFN1

    for (int i = 0; i < 2; i++) {
        const size_t wofD = (size_t)i * Dm * Dm;
        const size_t wofF = (size_t)i * Dm * DFFv;

        gemm_tf32<0><<<gP, 256>>>(qbuf, WQ + wofD, bQ + i * Dm, QH, Mrows, Dm, Dm);
        gemm_tf32<0><<<gP, 256>>>(k_in, WK + wofD, bK + i * Dm, KH, Mrows, Dm, Dm);
        gemm_tf32<0><<<gP, 256>>>(v_in, WV + wofD, bV + i * Dm, VH, Mrows, Dm, Dm);

        const float* prev = (i == 0) ? nullptr : S0;
        float* Sout = (i == 0) ? S0 : SW;
        scores_tf32<<<dim3(SKv / 64, SQv / 64, Bz * Hh), 128>>>(QH, KH, scale, extra, i, prev, Sout);
        softmax_kernel<<<Bz * Hh * SQv, 256>>>(Sout, SW);
        pv_tf32<<<dim3(SQv / 64, Bz * Hh), 128>>>(SW, VH, QH);   // QH reused as attn-out

        gemm_tf32<0><<<gP, 256>>>(QH, WO + wofD, bO + i * Dm, ATT, Mrows, Dm, Dm);
        addnorm_kernel<<<Mrows, 256>>>(qbuf, ATT, gA + i, ln1g + (size_t)i * Dm, ln1b + (size_t)i * Dm);

        gemm_tf32<1><<<gF1, 256>>>(qbuf, Wf1 + wofF, bf1 + i * DFFv, F1, Mrows, DFFv, Dm);
        gemm_tf32<0><<<gP, 256>>>(F1, Wf2 + wofF, bf2 + i * Dm, ATT, Mrows, Dm, DFFv);
        addnorm_kernel<<<Mrows, 256>>>(qbuf, ATT, gF + i, ln2g + (size_t)i * Dm, ln2b + (size_t)i * Dm);
    }
}

// round 7
// speedup vs baseline: 2.3606x; 1.1899x over previous
#include <cuda_runtime.h>
#include <math.h>
#include <stdint.h>

// Problem constants
#define Bz   8
#define SQv  1024
#define SKv  1024
#define Dm   512
#define Hh   8
#define HDv  64
#define DFFv 2048
#define Mrows 8192   // B*SQ == B*SK

// Dense GEMM tiling
#define BM 128
#define BN 128
#define BK 16

// ---------------- scratch (static device memory; no runtime allocation) ----------------
__device__ float g_QH[4194304];     // [8192,512]
__device__ float g_KH[4194304];
__device__ float g_VH[4194304];
__device__ float g_ATT[4194304];
__device__ float g_F1[16777216];    // [8192,2048]
__device__ float g_S0[67108864];    // layer-0 pre-softmax scores [B,H,SQ,SK]
__device__ float g_SW[67108864];    // working scores / probabilities

// ---------------- tf32 helpers ---------------------------------------------------------
__device__ __forceinline__ unsigned f2tf(float x) {
    unsigned u;
    asm("cvt.rna.tf32.f32 %0, %1;" : "=r"(u) : "f"(x));
    return u;
}

__device__ __forceinline__ void mma_tf32(float c[4], const unsigned a[4], const unsigned b[2]) {
    asm volatile(
        "mma.sync.aligned.m16n8k8.row.col.f32.tf32.tf32.f32 "
        "{%0,%1,%2,%3}, {%4,%5,%6,%7}, {%8,%9}, {%0,%1,%2,%3};\n"
        : "+f"(c[0]), "+f"(c[1]), "+f"(c[2]), "+f"(c[3])
        : "r"(a[0]), "r"(a[1]), "r"(a[2]), "r"(a[3]), "r"(b[0]), "r"(b[1]));
}

// ---------------- block reductions (blockDim.x == 256 assumed) ----------------
__device__ __forceinline__ float blk_sum256(float v) {
    __shared__ float s[8];
    int tid = threadIdx.x;
    #pragma unroll
    for (int o = 16; o > 0; o >>= 1) v += __shfl_xor_sync(0xffffffffu, v, o);
    __syncthreads();
    if ((tid & 31) == 0) s[tid >> 5] = v;
    __syncthreads();
    float r = 0.f;
    #pragma unroll
    for (int i = 0; i < 8; i++) r += s[i];
    return r;
}

__device__ __forceinline__ float blk_max256(float v) {
    __shared__ float s[8];
    int tid = threadIdx.x;
    #pragma unroll
    for (int o = 16; o > 0; o >>= 1) v = fmaxf(v, __shfl_xor_sync(0xffffffffu, v, o));
    __syncthreads();
    if ((tid & 31) == 0) s[tid >> 5] = v;
    __syncthreads();
    float r = -3.4e38f;
    #pragma unroll
    for (int i = 0; i < 8; i++) r = fmaxf(r, s[i]);
    return r;
}

// ---------------- dense GEMM (tf32): C = A[M,K] @ W[K,N] + bias (+GELU) ----------------
// CTA 128x128, 128 threads = 4 warps (2x2), warp tile 64x64, BK=16,
// double-buffered smem, one __syncthreads per K-step.
template<int ACT>
__global__ __launch_bounds__(128)
void gemm_tf32(const float* __restrict__ A, const float* __restrict__ W,
               const float* __restrict__ bias, float* __restrict__ C,
               int M, int N, int K)
{
    __shared__ unsigned As[2][BM][BK + 4];   // [m][k], stride 20: LDS bank = 20g+tg, all-distinct
    __shared__ unsigned Ws[2][BK][BN + 8];   // [k][n], stride 136: bank = 8tg+g, all-distinct

    const int tid  = threadIdx.x;
    const int lane = tid & 31, warp = tid >> 5;
    const int wm = (warp >> 1) * 64;     // 0 or 64
    const int wn = (warp & 1) * 64;      // 0 or 64
    const int g = lane >> 2, tg = lane & 3;
    const int bm = blockIdx.y * BM, bn = blockIdx.x * BN;

    float acc[4][8][4];
    #pragma unroll
    for (int i = 0; i < 4; i++)
        #pragma unroll
        for (int j = 0; j < 8; j++)
            #pragma unroll
            for (int r = 0; r < 4; r++) acc[i][j][r] = 0.f;

    // loaders: A tile 128x16 = 512 float4 -> 4/thread; W tile 16x128 = 512 float4 -> 4/thread
    float4 aR[4], wR[4];
    #pragma unroll
    for (int i = 0; i < 4; i++) {
        int f = tid + i * 128;
        aR[i] = *(const float4*)&A[(size_t)(bm + (f >> 2)) * K + ((f & 3) * 4)];
        wR[i] = *(const float4*)&W[(size_t)(f >> 5) * N + bn + ((f & 31) * 4)];
    }
    #pragma unroll
    for (int i = 0; i < 4; i++) {
        int f = tid + i * 128;
        *(uint4*)&As[0][f >> 2][(f & 3) * 4] =
            make_uint4(f2tf(aR[i].x), f2tf(aR[i].y), f2tf(aR[i].z), f2tf(aR[i].w));
        *(uint4*)&Ws[0][f >> 5][(f & 31) * 4] =
            make_uint4(f2tf(wR[i].x), f2tf(wR[i].y), f2tf(wR[i].z), f2tf(wR[i].w));
    }
    __syncthreads();

    const int nt = K / BK;
    for (int it = 0; it < nt; it++) {
        const int cur = it & 1;
        if (it + 1 < nt) {
            int kt = (it + 1) * BK;
            #pragma unroll
            for (int i = 0; i < 4; i++) {
                int f = tid + i * 128;
                aR[i] = *(const float4*)&A[(size_t)(bm + (f >> 2)) * K + kt + ((f & 3) * 4)];
                wR[i] = *(const float4*)&W[(size_t)(kt + (f >> 5)) * N + bn + ((f & 31) * 4)];
            }
        }
        #pragma unroll
        for (int ks = 0; ks < BK; ks += 8) {
            unsigned af[4][4], bf[8][2];
            #pragma unroll
            for (int mi = 0; mi < 4; mi++) {
                int r = wm + mi * 16 + g;
                af[mi][0] = As[cur][r][ks + tg];
                af[mi][1] = As[cur][r + 8][ks + tg];
                af[mi][2] = As[cur][r][ks + tg + 4];
                af[mi][3] = As[cur][r + 8][ks + tg + 4];
            }
            #pragma unroll
            for (int nj = 0; nj < 8; nj++) {
                int c = wn + nj * 8 + g;
                bf[nj][0] = Ws[cur][ks + tg][c];
                bf[nj][1] = Ws[cur][ks + tg + 4][c];
            }
            #pragma unroll
            for (int mi = 0; mi < 4; mi++)
                #pragma unroll
                for (int nj = 0; nj < 8; nj++)
                    mma_tf32(acc[mi][nj], af[mi], bf[nj]);
        }
        if (it + 1 < nt) {
            const int nxt = cur ^ 1;
            #pragma unroll
            for (int i = 0; i < 4; i++) {
                int f = tid + i * 128;
                *(uint4*)&As[nxt][f >> 2][(f & 3) * 4] =
                    make_uint4(f2tf(aR[i].x), f2tf(aR[i].y), f2tf(aR[i].z), f2tf(aR[i].w));
                *(uint4*)&Ws[nxt][f >> 5][(f & 31) * 4] =
                    make_uint4(f2tf(wR[i].x), f2tf(wR[i].y), f2tf(wR[i].z), f2tf(wR[i].w));
            }
            __syncthreads();
        }
    }

    // epilogue
    #pragma unroll
    for (int mi = 0; mi < 4; mi++) {
        #pragma unroll
        for (int nj = 0; nj < 8; nj++) {
            int row = bm + wm + mi * 16 + g;
            int col = bn + wn + nj * 8 + tg * 2;
            float b0 = bias[col], b1 = bias[col + 1];
            float2 v0 = make_float2(acc[mi][nj][0] + b0, acc[mi][nj][1] + b1);
            float2 v1 = make_float2(acc[mi][nj][2] + b0, acc[mi][nj][3] + b1);
            if (ACT == 1) {
                v0.x = 0.5f * v0.x * (1.f + erff(v0.x * 0.7071067811865475f));
                v0.y = 0.5f * v0.y * (1.f + erff(v0.y * 0.7071067811865475f));
                v1.x = 0.5f * v1.x * (1.f + erff(v1.x * 0.7071067811865475f));
                v1.y = 0.5f * v1.y * (1.f + erff(v1.y * 0.7071067811865475f));
            }
            *(float2*)&C[(size_t)row * N + col]       = v0;
            *(float2*)&C[(size_t)(row + 8) * N + col] = v1;
        }
    }
}

// ---------------- attention scores: S = eff*(Q K^T) (+prev) ----------------------------
// CTA = 64 q-rows, loops over all SK. Q fragments held in registers the whole kernel
// (zero A-side LDS in the mainloop, zero Q gmem re-reads).
// 128 threads = 4 warps (2q x 2k), warp tile 32x32.
__global__ __launch_bounds__(128)
void scores_tf32(const float* __restrict__ QH, const float* __restrict__ KH,
                 const float* __restrict__ scale, const float* __restrict__ extra,
                 int layer, const float* __restrict__ prev, float* __restrict__ S)
{
    __shared__ unsigned Qs[64][72];   // [q][d], stride 72: bank = 8g+tg, all-distinct
    __shared__ unsigned Ks[64][72];   // [k][d]
    const int tid = threadIdx.x;
    const int lane = tid & 31, warp = tid >> 5;
    const int wq = (warp >> 1) * 32, wk = (warp & 1) * 32;
    const int g = lane >> 2, tg = lane & 3;
    const int bh = blockIdx.y, b = bh >> 3, h = bh & 7;
    const int q0 = blockIdx.x * 64;
    const float* Qb = QH + (size_t)b * SQv * Dm + h * HDv;
    const float* Kb = KH + (size_t)b * SKv * Dm + h * HDv;

    // load Q tile 64x64 once
    #pragma unroll
    for (int i = 0; i < 8; i++) {
        int f = tid + i * 128;
        int r = f >> 4, c = (f & 15) * 4;
        float4 qv = *(const float4*)&Qb[(size_t)(q0 + r) * Dm + c];
        *(uint4*)&Qs[r][c] = make_uint4(f2tf(qv.x), f2tf(qv.y), f2tf(qv.z), f2tf(qv.w));
    }
    __syncthreads();

    // hold all Q fragments in registers: 8 k-chunks x 2 m-frags x 4 regs = 64 regs
    unsigned qf[8][2][4];
    #pragma unroll
    for (int kc = 0; kc < 8; kc++)
        #pragma unroll
        for (int mi = 0; mi < 2; mi++) {
            int r = wq + mi * 16 + g;
            qf[kc][mi][0] = Qs[r][kc * 8 + tg];
            qf[kc][mi][1] = Qs[r + 8][kc * 8 + tg];
            qf[kc][mi][2] = Qs[r][kc * 8 + tg + 4];
            qf[kc][mi][3] = Qs[r + 8][kc * 8 + tg + 4];
        }

    float e = extra[layer];
    e = fminf(fmaxf(e, 0.01f), 50.0f);
    const float eff = scale[layer] * e;

    for (int k0 = 0; k0 < SKv; k0 += 64) {
        __syncthreads();
        #pragma unroll
        for (int i = 0; i < 8; i++) {
            int f = tid + i * 128;
            int r = f >> 4, c = (f & 15) * 4;
            float4 kv = *(const float4*)&Kb[(size_t)(k0 + r) * Dm + c];
            *(uint4*)&Ks[r][c] = make_uint4(f2tf(kv.x), f2tf(kv.y), f2tf(kv.z), f2tf(kv.w));
        }
        __syncthreads();

        float acc[2][4][4];
        #pragma unroll
        for (int i = 0; i < 2; i++)
            #pragma unroll
            for (int j = 0; j < 4; j++)
                #pragma unroll
                for (int r = 0; r < 4; r++) acc[i][j][r] = 0.f;

        #pragma unroll
        for (int kc = 0; kc < 8; kc++) {
            unsigned bf[4][2];
            #pragma unroll
            for (int nj = 0; nj < 4; nj++) {
                int c = wk + nj * 8 + g;
                bf[nj][0] = Ks[c][kc * 8 + tg];
                bf[nj][1] = Ks[c][kc * 8 + tg + 4];
            }
            #pragma unroll
            for (int mi = 0; mi < 2; mi++)
                #pragma unroll
                for (int nj = 0; nj < 4; nj++)
                    mma_tf32(acc[mi][nj], qf[kc][mi], bf[nj]);
        }

        #pragma unroll
        for (int mi = 0; mi < 2; mi++) {
            #pragma unroll
            for (int nj = 0; nj < 4; nj++) {
                int row = q0 + wq + mi * 16 + g;
                int col = k0 + wk + nj * 8 + tg * 2;
                size_t b0 = ((size_t)bh * SQv + row) * SKv + col;
                size_t b1 = b0 + (size_t)8 * SKv;
                float2 p0 = prev ? *(const float2*)&prev[b0] : make_float2(0.f, 0.f);
                float2 p1 = prev ? *(const float2*)&prev[b1] : make_float2(0.f, 0.f);
                *(float2*)&S[b0] = make_float2(fmaf(acc[mi][nj][0], eff, p0.x),
                                               fmaf(acc[mi][nj][1], eff, p0.y));
                *(float2*)&S[b1] = make_float2(fmaf(acc[mi][nj][2], eff, p1.x),
                                               fmaf(acc[mi][nj][3], eff, p1.y));
            }
        }
    }
}

// ---------------- P@V: O[b,q,h*64+d] = sum_k P[b,h,q,k] * VH[b,k,h*64+d] ---------------
// CTA 128q x 64d, 128 threads = 4 warps (4q), warp tile 32q x 64d (LDS/mma = 1.5).
// k-tiles of 32; Ps stride 40 & Vs stride 72 are bank-conflict-free.
__global__ __launch_bounds__(128)
void pv_tf32(const float* __restrict__ P, const float* __restrict__ VH,
             float* __restrict__ O)
{
    __shared__ unsigned Ps[128][40];   // [q][k], stride 40: bank = 8g+tg pattern
    __shared__ unsigned Vs[32][72];    // [k][d], stride 72
    const int tid = threadIdx.x;
    const int lane = tid & 31, warp = tid >> 5;
    const int wq = warp * 32;
    const int g = lane >> 2, tg = lane & 3;
    const int bh = blockIdx.y, b = bh >> 3, h = bh & 7;
    const int q0 = blockIdx.x * 128;
    const float* Pb = P + (size_t)bh * SQv * SKv;
    const float* Vb = VH + (size_t)b * SKv * Dm + h * HDv;

    float acc[2][8][4];
    #pragma unroll
    for (int i = 0; i < 2; i++)
        #pragma unroll
        for (int j = 0; j < 8; j++)
            #pragma unroll
            for (int r = 0; r < 4; r++) acc[i][j][r] = 0.f;

    for (int kt = 0; kt < SKv; kt += 32) {
        __syncthreads();
        // P tile 128x32 = 1024 float4 -> 8/thread
        #pragma unroll
        for (int i = 0; i < 8; i++) {
            int f = tid + i * 128;
            int r = f >> 3, c = (f & 7) * 4;
            float4 pv = *(const float4*)&Pb[(size_t)(q0 + r) * SKv + kt + c];
            *(uint4*)&Ps[r][c] = make_uint4(f2tf(pv.x), f2tf(pv.y), f2tf(pv.z), f2tf(pv.w));
        }
        // V tile 32x64 = 512 float4 -> 4/thread
        #pragma unroll
        for (int i = 0; i < 4; i++) {
            int f = tid + i * 128;
            int r = f >> 4, c = (f & 15) * 4;
            float4 vv = *(const float4*)&Vb[(size_t)(kt + r) * Dm + c];
            *(uint4*)&Vs[r][c] = make_uint4(f2tf(vv.x), f2tf(vv.y), f2tf(vv.z), f2tf(vv.w));
        }
        __syncthreads();

        #pragma unroll
        for (int kc = 0; kc < 4; kc++) {
            unsigned af[2][4], bf[8][2];
            #pragma unroll
            for (int mi = 0; mi < 2; mi++) {
                int r = wq + mi * 16 + g;
                af[mi][0] = Ps[r][kc * 8 + tg];
                af[mi][1] = Ps[r + 8][kc * 8 + tg];
                af[mi][2] = Ps[r][kc * 8 + tg + 4];
                af[mi][3] = Ps[r + 8][kc * 8 + tg + 4];
            }
            #pragma unroll
            for (int nj = 0; nj < 8; nj++) {
                int c = nj * 8 + g;
                bf[nj][0] = Vs[kc * 8 + tg][c];
                bf[nj][1] = Vs[kc * 8 + tg + 4][c];
            }
            #pragma unroll
            for (int mi = 0; mi < 2; mi++)
                #pragma unroll
                for (int nj = 0; nj < 8; nj++)
                    mma_tf32(acc[mi][nj], af[mi], bf[nj]);
        }
    }

    float* Ob = O + (size_t)b * SQv * Dm + h * HDv;
    #pragma unroll
    for (int mi = 0; mi < 2; mi++) {
        #pragma unroll
        for (int nj = 0; nj < 8; nj++) {
            int row = q0 + wq + mi * 16 + g;
            int col = nj * 8 + tg * 2;
            *(float2*)&Ob[(size_t)row * Dm + col] =
                make_float2(acc[mi][nj][0], acc[mi][nj][1]);
            *(float2*)&Ob[(size_t)(row + 8) * Dm + col] =
                make_float2(acc[mi][nj][2], acc[mi][nj][3]);
        }
    }
}

// ---------------- row softmax over SK=1024, one block per row -------------------------
__global__ __launch_bounds__(256)
void softmax_kernel(const float* __restrict__ S, float* __restrict__ P)
{
    const size_t row = blockIdx.x;
    const int tid = threadIdx.x;
    float4 v = *(const float4*)&S[row * SKv + tid * 4];
    float m = fmaxf(fmaxf(v.x, v.y), fmaxf(v.z, v.w));
    m = blk_max256(m);
    float e0 = expf(v.x - m), e1 = expf(v.y - m), e2 = expf(v.z - m), e3 = expf(v.w - m);
    float s = blk_sum256(e0 + e1 + e2 + e3);
    float inv = 1.f / s;
    float4 o = make_float4(e0 * inv, e1 * inv, e2 * inv, e3 * inv);
    *(float4*)&P[row * SKv + tid * 4] = o;
}

// ---------------- gated residual + post-LayerNorm (in-place on q) ----------------------
__global__ __launch_bounds__(256)
void addnorm_kernel(float* __restrict__ q, const float* __restrict__ delta,
                    const float* __restrict__ gate, const float* __restrict__ g,
                    const float* __restrict__ bb)
{
    const size_t row = blockIdx.x;
    const int tid = threadIdx.x;
    const float gt = gate[0];
    const float sp = (gt > 20.f) ? gt : log1pf(expf(gt));   // softplus

    float2 x = *(float2*)&q[row * Dm + tid * 2];
    float2 dd = *(const float2*)&delta[row * Dm + tid * 2];
    float y0 = x.x + sp * dd.x;
    float y1 = x.y + sp * dd.y;

    float s = blk_sum256(y0 + y1);
    float mu = s * (1.f / 512.f);
    float s2 = blk_sum256((y0 - mu) * (y0 - mu) + (y1 - mu) * (y1 - mu));
    float inv = rsqrtf(s2 * (1.f / 512.f) + 1e-5f);

    float2 o;
    o.x = (y0 - mu) * inv * g[tid * 2 + 0] + bb[tid * 2 + 0];
    o.y = (y1 - mu) * inv * g[tid * 2 + 1] + bb[tid * 2 + 1];
    *(float2*)&q[row * Dm + tid * 2] = o;
}

// ---------------- launcher -------------------------------------------------------------
extern "C" void kernel_launch(void* const* d_in, const int* in_sizes, int n_in,
                              void* d_out, int out_size)
{
    (void)in_sizes; (void)n_in; (void)out_size;
    const float* q_in  = (const float*)d_in[0];
    const float* k_in  = (const float*)d_in[1];
    const float* v_in  = (const float*)d_in[2];
    const float* WQ    = (const float*)d_in[3];
    const float* bQ    = (const float*)d_in[4];
    const float* WK    = (const float*)d_in[5];
    const float* bK    = (const float*)d_in[6];
    const float* WV    = (const float*)d_in[7];
    const float* bV    = (const float*)d_in[8];
    const float* WO    = (const float*)d_in[9];
    const float* bO    = (const float*)d_in[10];
    const float* Wf1   = (const float*)d_in[11];
    const float* bf1   = (const float*)d_in[12];
    const float* Wf2   = (const float*)d_in[13];
    const float* bf2   = (const float*)d_in[14];
    const float* ln1g  = (const float*)d_in[15];
    const float* ln1b  = (const float*)d_in[16];
    const float* ln2g  = (const float*)d_in[17];
    const float* ln2b  = (const float*)d_in[18];
    const float* scale = (const float*)d_in[19];
    const float* extra = (const float*)d_in[20];
    const float* gA    = (const float*)d_in[21];
    const float* gF    = (const float*)d_in[22];

    float *QH, *KH, *VH, *ATT, *F1, *S0, *SW;
    cudaGetSymbolAddress((void**)&QH, g_QH);
    cudaGetSymbolAddress((void**)&KH, g_KH);
    cudaGetSymbolAddress((void**)&VH, g_VH);
    cudaGetSymbolAddress((void**)&ATT, g_ATT);
    cudaGetSymbolAddress((void**)&F1, g_F1);
    cudaGetSymbolAddress((void**)&S0, g_S0);
    cudaGetSymbolAddress((void**)&SW, g_SW);

    float* qbuf = (float*)d_out;   // q lives in d_out the whole time
    cudaMemcpyAsync(qbuf, q_in, (size_t)Mrows * Dm * sizeof(float),
                    cudaMemcpyDeviceToDevice);

    const dim3 gP(Dm / BN, Mrows / BM);        // (4, 64)  N=512 GEMMs
    const dim3 gF1(DFFv / BN, Mrows / BM);     // (16, 64) FFN1

    for (int i = 0; i < 2; i++) {
        const size_t wofD = (size_t)i * Dm * Dm;
        const size_t wofF = (size_t)i * Dm * DFFv;

        gemm_tf32<0><<<gP, 128>>>(qbuf, WQ + wofD, bQ + i * Dm, QH, Mrows, Dm, Dm);
        gemm_tf32<0><<<gP, 128>>>(k_in, WK + wofD, bK + i * Dm, KH, Mrows, Dm, Dm);
        gemm_tf32<0><<<gP, 128>>>(v_in, WV + wofD, bV + i * Dm, VH, Mrows, Dm, Dm);

        const float* prev = (i == 0) ? nullptr : S0;
        float* Sout = (i == 0) ? S0 : SW;
        scores_tf32<<<dim3(SQv / 64, Bz * Hh), 128>>>(QH, KH, scale, extra, i, prev, Sout);
        softmax_kernel<<<Bz * Hh * SQv, 256>>>(Sout, SW);
        pv_tf32<<<dim3(SQv / 128, Bz * Hh), 128>>>(SW, VH, QH);   // QH reused as attn-out

        gemm_tf32<0><<<gP, 128>>>(QH, WO + wofD, bO + i * Dm, ATT, Mrows, Dm, Dm);
        addnorm_kernel<<<Mrows, 256>>>(qbuf, ATT, gA + i, ln1g + (size_t)i * Dm, ln1b + (size_t)i * Dm);

        gemm_tf32<1><<<gF1, 128>>>(qbuf, Wf1 + wofF, bf1 + i * DFFv, F1, Mrows, DFFv, Dm);
        gemm_tf32<0><<<gP, 128>>>(F1, Wf2 + wofF, bf2 + i * Dm, ATT, Mrows, Dm, DFFv);
        addnorm_kernel<<<Mrows, 256>>>(qbuf, ATT, gF + i, ln2g + (size_t)i * Dm, ln2b + (size_t)i * Dm);
    }
}

// round 8
// speedup vs baseline: 2.7520x; 1.1658x over previous
#include <cuda_runtime.h>
#include <math.h>
#include <stdint.h>

// Problem constants
#define Bz   8
#define SQv  1024
#define SKv  1024
#define Dm   512
#define Hh   8
#define HDv  64
#define DFFv 2048
#define Mrows 8192   // B*SQ == B*SK

// Dense GEMM tiling
#define BM 128
#define BN 128
#define BK 16

// ---------------- scratch (static device memory; no runtime allocation) ----------------
__device__ float g_QH[4194304];     // [8192,512]
__device__ float g_KH[4194304];
__device__ float g_VH[4194304];
__device__ float g_ATT[4194304];
__device__ float g_F1[16777216];    // [8192,2048]
__device__ float g_S0[67108864];    // layer-0 pre-softmax scores [B,H,SQ,SK]

// ---------------- tf32 helpers ---------------------------------------------------------
__device__ __forceinline__ unsigned f2tf(float x) {
    unsigned u;
    asm("cvt.rna.tf32.f32 %0, %1;" : "=r"(u) : "f"(x));
    return u;
}

__device__ __forceinline__ void mma_tf32(float c[4], const unsigned a[4], const unsigned b[2]) {
    asm volatile(
        "mma.sync.aligned.m16n8k8.row.col.f32.tf32.tf32.f32 "
        "{%0,%1,%2,%3}, {%4,%5,%6,%7}, {%8,%9}, {%0,%1,%2,%3};\n"
        : "+f"(c[0]), "+f"(c[1]), "+f"(c[2]), "+f"(c[3])
        : "r"(a[0]), "r"(a[1]), "r"(a[2]), "r"(a[3]), "r"(b[0]), "r"(b[1]));
}

// ---------------- block reductions (blockDim.x == 256 assumed) ----------------
__device__ __forceinline__ float blk_sum256(float v) {
    __shared__ float s[8];
    int tid = threadIdx.x;
    #pragma unroll
    for (int o = 16; o > 0; o >>= 1) v += __shfl_xor_sync(0xffffffffu, v, o);
    __syncthreads();
    if ((tid & 31) == 0) s[tid >> 5] = v;
    __syncthreads();
    float r = 0.f;
    #pragma unroll
    for (int i = 0; i < 8; i++) r += s[i];
    return r;
}

// ---------------- dense GEMM (tf32): C = A[M,K] @ W[K,N] + bias (+GELU) ----------------
// CTA 128x128, 128 threads = 4 warps (2x2), warp tile 64x64, BK=16,
// double-buffered smem, one __syncthreads per K-step.
template<int ACT>
__global__ __launch_bounds__(128)
void gemm_tf32(const float* __restrict__ A, const float* __restrict__ W,
               const float* __restrict__ bias, float* __restrict__ C,
               int M, int N, int K)
{
    __shared__ unsigned As[2][BM][BK + 4];   // [m][k], stride 20: LDS conflict-free
    __shared__ unsigned Ws[2][BK][BN + 8];   // [k][n], stride 136: LDS conflict-free

    const int tid  = threadIdx.x;
    const int lane = tid & 31, warp = tid >> 5;
    const int wm = (warp >> 1) * 64;
    const int wn = (warp & 1) * 64;
    const int g = lane >> 2, tg = lane & 3;
    const int bm = blockIdx.y * BM, bn = blockIdx.x * BN;

    float acc[4][8][4];
    #pragma unroll
    for (int i = 0; i < 4; i++)
        #pragma unroll
        for (int j = 0; j < 8; j++)
            #pragma unroll
            for (int r = 0; r < 4; r++) acc[i][j][r] = 0.f;

    float4 aR[4], wR[4];
    #pragma unroll
    for (int i = 0; i < 4; i++) {
        int f = tid + i * 128;
        aR[i] = *(const float4*)&A[(size_t)(bm + (f >> 2)) * K + ((f & 3) * 4)];
        wR[i] = *(const float4*)&W[(size_t)(f >> 5) * N + bn + ((f & 31) * 4)];
    }
    #pragma unroll
    for (int i = 0; i < 4; i++) {
        int f = tid + i * 128;
        *(uint4*)&As[0][f >> 2][(f & 3) * 4] =
            make_uint4(f2tf(aR[i].x), f2tf(aR[i].y), f2tf(aR[i].z), f2tf(aR[i].w));
        *(uint4*)&Ws[0][f >> 5][(f & 31) * 4] =
            make_uint4(f2tf(wR[i].x), f2tf(wR[i].y), f2tf(wR[i].z), f2tf(wR[i].w));
    }
    __syncthreads();

    const int nt = K / BK;
    for (int it = 0; it < nt; it++) {
        const int cur = it & 1;
        if (it + 1 < nt) {
            int kt = (it + 1) * BK;
            #pragma unroll
            for (int i = 0; i < 4; i++) {
                int f = tid + i * 128;
                aR[i] = *(const float4*)&A[(size_t)(bm + (f >> 2)) * K + kt + ((f & 3) * 4)];
                wR[i] = *(const float4*)&W[(size_t)(kt + (f >> 5)) * N + bn + ((f & 31) * 4)];
            }
        }
        #pragma unroll
        for (int ks = 0; ks < BK; ks += 8) {
            unsigned af[4][4], bf[8][2];
            #pragma unroll
            for (int mi = 0; mi < 4; mi++) {
                int r = wm + mi * 16 + g;
                af[mi][0] = As[cur][r][ks + tg];
                af[mi][1] = As[cur][r + 8][ks + tg];
                af[mi][2] = As[cur][r][ks + tg + 4];
                af[mi][3] = As[cur][r + 8][ks + tg + 4];
            }
            #pragma unroll
            for (int nj = 0; nj < 8; nj++) {
                int c = wn + nj * 8 + g;
                bf[nj][0] = Ws[cur][ks + tg][c];
                bf[nj][1] = Ws[cur][ks + tg + 4][c];
            }
            #pragma unroll
            for (int mi = 0; mi < 4; mi++)
                #pragma unroll
                for (int nj = 0; nj < 8; nj++)
                    mma_tf32(acc[mi][nj], af[mi], bf[nj]);
        }
        if (it + 1 < nt) {
            const int nxt = cur ^ 1;
            #pragma unroll
            for (int i = 0; i < 4; i++) {
                int f = tid + i * 128;
                *(uint4*)&As[nxt][f >> 2][(f & 3) * 4] =
                    make_uint4(f2tf(aR[i].x), f2tf(aR[i].y), f2tf(aR[i].z), f2tf(aR[i].w));
                *(uint4*)&Ws[nxt][f >> 5][(f & 31) * 4] =
                    make_uint4(f2tf(wR[i].x), f2tf(wR[i].y), f2tf(wR[i].z), f2tf(wR[i].w));
            }
            __syncthreads();
        }
    }

    #pragma unroll
    for (int mi = 0; mi < 4; mi++) {
        #pragma unroll
        for (int nj = 0; nj < 8; nj++) {
            int row = bm + wm + mi * 16 + g;
            int col = bn + wn + nj * 8 + tg * 2;
            float b0 = bias[col], b1 = bias[col + 1];
            float2 v0 = make_float2(acc[mi][nj][0] + b0, acc[mi][nj][1] + b1);
            float2 v1 = make_float2(acc[mi][nj][2] + b0, acc[mi][nj][3] + b1);
            if (ACT == 1) {
                v0.x = 0.5f * v0.x * (1.f + erff(v0.x * 0.7071067811865475f));
                v0.y = 0.5f * v0.y * (1.f + erff(v0.y * 0.7071067811865475f));
                v1.x = 0.5f * v1.x * (1.f + erff(v1.x * 0.7071067811865475f));
                v1.y = 0.5f * v1.y * (1.f + erff(v1.y * 0.7071067811865475f));
            }
            *(float2*)&C[(size_t)row * N + col]       = v0;
            *(float2*)&C[(size_t)(row + 8) * N + col] = v1;
        }
    }
}

// ---------------- fused attention: scores (+prev / +store S0) + online softmax + P@V ---
// CTA = 64 q-rows of one (b,h). 128 threads = 4 warps, each warp owns 16 q-rows.
// K/V consumed in 32-row tiles; Q fragments register-resident; probabilities never
// touch gmem (P round-trips through a per-warp smem buffer, __syncwarp only).
// layer 0: writes raw scaled scores to outS. layer 1: reads prevS, writes no scores.
__global__ __launch_bounds__(128)
void attn_fused(const float* __restrict__ QH, const float* __restrict__ KH,
                const float* __restrict__ VH, const float* __restrict__ scale,
                const float* __restrict__ extra, int layer,
                const float* __restrict__ prevS, float* __restrict__ outS,
                float* __restrict__ O)
{
    __shared__ unsigned Qs[64][72];      // [q][d]
    __shared__ unsigned Ks[32][72];      // [k][d]
    __shared__ unsigned Vs[32][72];      // [k][d]
    __shared__ unsigned Ps[4][16][40];   // per-warp P buffer [q][k]

    const int tid = threadIdx.x;
    const int lane = tid & 31, warp = tid >> 5;
    const int g = lane >> 2, tg = lane & 3;
    const int wq = warp * 16;
    const int bh = blockIdx.y, b = bh >> 3, h = bh & 7;
    const int q0 = blockIdx.x * 64;
    const float* Qb = QH + (size_t)b * SQv * Dm + h * HDv;
    const float* Kb = KH + (size_t)b * SKv * Dm + h * HDv;
    const float* Vb = VH + (size_t)b * SKv * Dm + h * HDv;

    // ---- load Q tile 64x64 once, stage fragments to registers ----
    #pragma unroll
    for (int i = 0; i < 8; i++) {
        int f = tid + i * 128;
        int r = f >> 4, c = (f & 15) * 4;
        float4 qv = *(const float4*)&Qb[(size_t)(q0 + r) * Dm + c];
        *(uint4*)&Qs[r][c] = make_uint4(f2tf(qv.x), f2tf(qv.y), f2tf(qv.z), f2tf(qv.w));
    }
    __syncthreads();
    unsigned qf[8][4];
    #pragma unroll
    for (int kc = 0; kc < 8; kc++) {
        qf[kc][0] = Qs[wq + g][kc * 8 + tg];
        qf[kc][1] = Qs[wq + g + 8][kc * 8 + tg];
        qf[kc][2] = Qs[wq + g][kc * 8 + tg + 4];
        qf[kc][3] = Qs[wq + g + 8][kc * 8 + tg + 4];
    }

    float e = extra[layer];
    e = fminf(fmaxf(e, 0.01f), 50.0f);
    const float eff = scale[layer] * e;

    float m0 = -INFINITY, m8 = -INFINITY, l0 = 0.f, l8 = 0.f;
    float oacc[8][4];
    #pragma unroll
    for (int j = 0; j < 8; j++)
        #pragma unroll
        for (int r = 0; r < 4; r++) oacc[j][r] = 0.f;

    // preload K/V tile 0
    float4 kR[4], vR[4];
    #pragma unroll
    for (int i = 0; i < 4; i++) {
        int f = tid + i * 128;
        int r = f >> 4, c = (f & 15) * 4;
        kR[i] = *(const float4*)&Kb[(size_t)r * Dm + c];
        vR[i] = *(const float4*)&Vb[(size_t)r * Dm + c];
    }
    #pragma unroll
    for (int i = 0; i < 4; i++) {
        int f = tid + i * 128;
        int r = f >> 4, c = (f & 15) * 4;
        *(uint4*)&Ks[r][c] = make_uint4(f2tf(kR[i].x), f2tf(kR[i].y), f2tf(kR[i].z), f2tf(kR[i].w));
        *(uint4*)&Vs[r][c] = make_uint4(f2tf(vR[i].x), f2tf(vR[i].y), f2tf(vR[i].z), f2tf(vR[i].w));
    }
    __syncthreads();

    const int row0 = q0 + wq + g;
    const size_t srow0 = ((size_t)bh * SQv + row0) * SKv;
    const size_t srow8 = srow0 + (size_t)8 * SKv;

    for (int it = 0; it < 32; it++) {
        const int kt = it * 32;
        // prefetch next K/V tile into registers
        if (it + 1 < 32) {
            int ktn = kt + 32;
            #pragma unroll
            for (int i = 0; i < 4; i++) {
                int f = tid + i * 128;
                int r = f >> 4, c = (f & 15) * 4;
                kR[i] = *(const float4*)&Kb[(size_t)(ktn + r) * Dm + c];
                vR[i] = *(const float4*)&Vb[(size_t)(ktn + r) * Dm + c];
            }
        }

        // ---- scores: s[nj] = Q(16) x K^T(32), d = 64 ----
        float s[4][4];
        #pragma unroll
        for (int j = 0; j < 4; j++)
            #pragma unroll
            for (int r = 0; r < 4; r++) s[j][r] = 0.f;
        #pragma unroll
        for (int kc = 0; kc < 8; kc++) {
            unsigned bf[4][2];
            #pragma unroll
            for (int nj = 0; nj < 4; nj++) {
                int c = nj * 8 + g;
                bf[nj][0] = Ks[c][kc * 8 + tg];
                bf[nj][1] = Ks[c][kc * 8 + tg + 4];
            }
            #pragma unroll
            for (int nj = 0; nj < 4; nj++)
                mma_tf32(s[nj], qf[kc], bf[nj]);
        }

        // ---- scale, add prev / store raw scores ----
        if (prevS) {
            #pragma unroll
            for (int nj = 0; nj < 4; nj++) {
                int col = kt + nj * 8 + tg * 2;
                float2 p0 = *(const float2*)&prevS[srow0 + col];
                float2 p8 = *(const float2*)&prevS[srow8 + col];
                s[nj][0] = fmaf(s[nj][0], eff, p0.x);
                s[nj][1] = fmaf(s[nj][1], eff, p0.y);
                s[nj][2] = fmaf(s[nj][2], eff, p8.x);
                s[nj][3] = fmaf(s[nj][3], eff, p8.y);
            }
        } else {
            #pragma unroll
            for (int nj = 0; nj < 4; nj++) {
                s[nj][0] *= eff; s[nj][1] *= eff; s[nj][2] *= eff; s[nj][3] *= eff;
                int col = kt + nj * 8 + tg * 2;
                *(float2*)&outS[srow0 + col] = make_float2(s[nj][0], s[nj][1]);
                *(float2*)&outS[srow8 + col] = make_float2(s[nj][2], s[nj][3]);
            }
        }

        // ---- online softmax update ----
        float tm0 = -INFINITY, tm8 = -INFINITY;
        #pragma unroll
        for (int nj = 0; nj < 4; nj++) {
            tm0 = fmaxf(tm0, fmaxf(s[nj][0], s[nj][1]));
            tm8 = fmaxf(tm8, fmaxf(s[nj][2], s[nj][3]));
        }
        tm0 = fmaxf(tm0, __shfl_xor_sync(0xffffffffu, tm0, 1));
        tm0 = fmaxf(tm0, __shfl_xor_sync(0xffffffffu, tm0, 2));
        tm8 = fmaxf(tm8, __shfl_xor_sync(0xffffffffu, tm8, 1));
        tm8 = fmaxf(tm8, __shfl_xor_sync(0xffffffffu, tm8, 2));

        float nm0 = fmaxf(m0, tm0), nm8 = fmaxf(m8, tm8);
        float c0 = __expf(m0 - nm0), c8 = __expf(m8 - nm8);
        float rs0 = 0.f, rs8 = 0.f;
        #pragma unroll
        for (int nj = 0; nj < 4; nj++) {
            s[nj][0] = __expf(s[nj][0] - nm0);
            s[nj][1] = __expf(s[nj][1] - nm0);
            s[nj][2] = __expf(s[nj][2] - nm8);
            s[nj][3] = __expf(s[nj][3] - nm8);
            rs0 += s[nj][0] + s[nj][1];
            rs8 += s[nj][2] + s[nj][3];
        }
        rs0 += __shfl_xor_sync(0xffffffffu, rs0, 1);
        rs0 += __shfl_xor_sync(0xffffffffu, rs0, 2);
        rs8 += __shfl_xor_sync(0xffffffffu, rs8, 1);
        rs8 += __shfl_xor_sync(0xffffffffu, rs8, 2);
        l0 = l0 * c0 + rs0;  l8 = l8 * c8 + rs8;
        m0 = nm0;  m8 = nm8;
        #pragma unroll
        for (int nj = 0; nj < 8; nj++) {
            oacc[nj][0] *= c0; oacc[nj][1] *= c0;
            oacc[nj][2] *= c8; oacc[nj][3] *= c8;
        }

        // ---- P: C-layout -> smem -> A-layout fragments (per-warp buffer) ----
        #pragma unroll
        for (int nj = 0; nj < 4; nj++) {
            Ps[warp][g][nj * 8 + tg * 2]         = f2tf(s[nj][0]);
            Ps[warp][g][nj * 8 + tg * 2 + 1]     = f2tf(s[nj][1]);
            Ps[warp][g + 8][nj * 8 + tg * 2]     = f2tf(s[nj][2]);
            Ps[warp][g + 8][nj * 8 + tg * 2 + 1] = f2tf(s[nj][3]);
        }
        __syncwarp();
        unsigned pf[4][4];
        #pragma unroll
        for (int kc = 0; kc < 4; kc++) {
            pf[kc][0] = Ps[warp][g][kc * 8 + tg];
            pf[kc][1] = Ps[warp][g + 8][kc * 8 + tg];
            pf[kc][2] = Ps[warp][g][kc * 8 + tg + 4];
            pf[kc][3] = Ps[warp][g + 8][kc * 8 + tg + 4];
        }

        // ---- O += P(16x32) @ V(32x64) ----
        #pragma unroll
        for (int kc = 0; kc < 4; kc++) {
            unsigned vb[8][2];
            #pragma unroll
            for (int nj = 0; nj < 8; nj++) {
                int c = nj * 8 + g;
                vb[nj][0] = Vs[kc * 8 + tg][c];
                vb[nj][1] = Vs[kc * 8 + tg + 4][c];
            }
            #pragma unroll
            for (int nj = 0; nj < 8; nj++)
                mma_tf32(oacc[nj], pf[kc], vb[nj]);
        }

        __syncthreads();   // all warps done reading Ks/Vs
        if (it + 1 < 32) {
            #pragma unroll
            for (int i = 0; i < 4; i++) {
                int f = tid + i * 128;
                int r = f >> 4, c = (f & 15) * 4;
                *(uint4*)&Ks[r][c] = make_uint4(f2tf(kR[i].x), f2tf(kR[i].y), f2tf(kR[i].z), f2tf(kR[i].w));
                *(uint4*)&Vs[r][c] = make_uint4(f2tf(vR[i].x), f2tf(vR[i].y), f2tf(vR[i].z), f2tf(vR[i].w));
            }
            __syncthreads();
        }
    }

    // ---- finalize: O /= l, write [b, q, h*64 + d] ----
    float i0 = 1.f / l0, i8 = 1.f / l8;
    float* Ob = O + (size_t)b * SQv * Dm + h * HDv;
    #pragma unroll
    for (int nj = 0; nj < 8; nj++) {
        int col = nj * 8 + tg * 2;
        *(float2*)&Ob[(size_t)row0 * Dm + col] =
            make_float2(oacc[nj][0] * i0, oacc[nj][1] * i0);
        *(float2*)&Ob[(size_t)(row0 + 8) * Dm + col] =
            make_float2(oacc[nj][2] * i8, oacc[nj][3] * i8);
    }
}

// ---------------- gated residual + post-LayerNorm (in-place on q) ----------------------
__global__ __launch_bounds__(256)
void addnorm_kernel(float* __restrict__ q, const float* __restrict__ delta,
                    const float* __restrict__ gate, const float* __restrict__ g,
                    const float* __restrict__ bb)
{
    const size_t row = blockIdx.x;
    const int tid = threadIdx.x;
    const float gt = gate[0];
    const float sp = (gt > 20.f) ? gt : log1pf(expf(gt));   // softplus

    float2 x = *(float2*)&q[row * Dm + tid * 2];
    float2 dd = *(const float2*)&delta[row * Dm + tid * 2];
    float y0 = x.x + sp * dd.x;
    float y1 = x.y + sp * dd.y;

    float s = blk_sum256(y0 + y1);
    float mu = s * (1.f / 512.f);
    float s2 = blk_sum256((y0 - mu) * (y0 - mu) + (y1 - mu) * (y1 - mu));
    float inv = rsqrtf(s2 * (1.f / 512.f) + 1e-5f);

    float2 o;
    o.x = (y0 - mu) * inv * g[tid * 2 + 0] + bb[tid * 2 + 0];
    o.y = (y1 - mu) * inv * g[tid * 2 + 1] + bb[tid * 2 + 1];
    *(float2*)&q[row * Dm + tid * 2] = o;
}

// ---------------- launcher -------------------------------------------------------------
extern "C" void kernel_launch(void* const* d_in, const int* in_sizes, int n_in,
                              void* d_out, int out_size)
{
    (void)in_sizes; (void)n_in; (void)out_size;
    const float* q_in  = (const float*)d_in[0];
    const float* k_in  = (const float*)d_in[1];
    const float* v_in  = (const float*)d_in[2];
    const float* WQ    = (const float*)d_in[3];
    const float* bQ    = (const float*)d_in[4];
    const float* WK    = (const float*)d_in[5];
    const float* bK    = (const float*)d_in[6];
    const float* WV    = (const float*)d_in[7];
    const float* bV    = (const float*)d_in[8];
    const float* WO    = (const float*)d_in[9];
    const float* bO    = (const float*)d_in[10];
    const float* Wf1   = (const float*)d_in[11];
    const float* bf1   = (const float*)d_in[12];
    const float* Wf2   = (const float*)d_in[13];
    const float* bf2   = (const float*)d_in[14];
    const float* ln1g  = (const float*)d_in[15];
    const float* ln1b  = (const float*)d_in[16];
    const float* ln2g  = (const float*)d_in[17];
    const float* ln2b  = (const float*)d_in[18];
    const float* scale = (const float*)d_in[19];
    const float* extra = (const float*)d_in[20];
    const float* gA    = (const float*)d_in[21];
    const float* gF    = (const float*)d_in[22];

    float *QH, *KH, *VH, *ATT, *F1, *S0;
    cudaGetSymbolAddress((void**)&QH, g_QH);
    cudaGetSymbolAddress((void**)&KH, g_KH);
    cudaGetSymbolAddress((void**)&VH, g_VH);
    cudaGetSymbolAddress((void**)&ATT, g_ATT);
    cudaGetSymbolAddress((void**)&F1, g_F1);
    cudaGetSymbolAddress((void**)&S0, g_S0);

    float* qbuf = (float*)d_out;   // q lives in d_out the whole time
    cudaMemcpyAsync(qbuf, q_in, (size_t)Mrows * Dm * sizeof(float),
                    cudaMemcpyDeviceToDevice);

    const dim3 gP(Dm / BN, Mrows / BM);        // (4, 64)  N=512 GEMMs
    const dim3 gF1(DFFv / BN, Mrows / BM);     // (16, 64) FFN1

    for (int i = 0; i < 2; i++) {
        const size_t wofD = (size_t)i * Dm * Dm;
        const size_t wofF = (size_t)i * Dm * DFFv;

        gemm_tf32<0><<<gP, 128>>>(qbuf, WQ + wofD, bQ + i * Dm, QH, Mrows, Dm, Dm);
        gemm_tf32<0><<<gP, 128>>>(k_in, WK + wofD, bK + i * Dm, KH, Mrows, Dm, Dm);
        gemm_tf32<0><<<gP, 128>>>(v_in, WV + wofD, bV + i * Dm, VH, Mrows, Dm, Dm);

        // fused scores(+prev/S0) + online softmax + P@V; attn-out overwrites QH
        const float* prev = (i == 0) ? nullptr : S0;
        float* Sout = (i == 0) ? S0 : nullptr;
        attn_fused<<<dim3(SQv / 64, Bz * Hh), 128>>>(QH, KH, VH, scale, extra, i,
                                                     prev, Sout, QH);

        gemm_tf32<0><<<gP, 128>>>(QH, WO + wofD, bO + i * Dm, ATT, Mrows, Dm, Dm);
        addnorm_kernel<<<Mrows, 256>>>(qbuf, ATT, gA + i, ln1g + (size_t)i * Dm, ln1b + (size_t)i * Dm);

        gemm_tf32<1><<<gF1, 128>>>(qbuf, Wf1 + wofF, bf1 + i * DFFv, F1, Mrows, DFFv, Dm);
        gemm_tf32<0><<<gP, 128>>>(F1, Wf2 + wofF, bf2 + i * Dm, ATT, Mrows, Dm, DFFv);
        addnorm_kernel<<<Mrows, 256>>>(qbuf, ATT, gF + i, ln2g + (size_t)i * Dm, ln2b + (size_t)i * Dm);
    }
}